// round 13
// baseline (speedup 1.0000x reference)
#include <cuda_runtime.h>

// Depthwise 3x3 conv, SAME padding, channel multiplier 2, NHWC fp32.
// x: [16,224,224,96], kernel: [3,3,1,2], bias: [192], out: [16,224,224,192]
// out[b,h,w,c*2+m] = sum_{dh,dw} x[b,h+dh-1,w+dw-1,c] * k[dh,dw,0,m] + bias[c*2+m]
//
// R12: R11 (h-streaming, depth-3 prefetch, running pointers, clamp-free main
// loop) + cache-policy tuning:
//   - output stores via st.global.cs (streaming, evict-first): write stream
//     never re-read -> stop it evicting the 3x-reused input rows from L2.
//   - input rows via __ldg (non-coherent path, explicit).
// Traffic/occupancy/structure identical to R11; targets DRAM R/W-mix
// efficiency (76.1% -> ~79%).

#define BATCH 16
#define HH 224
#define WW 224
#define CIN 96
#define COUT 192
#define HCH 56   // h rows per CTA (224/56 = 4 chunks)

__device__ __forceinline__ void stcs4(float* p, float4 v) {
    asm volatile("st.global.cs.v4.f32 [%0], {%1, %2, %3, %4};"
                 :: "l"(p), "f"(v.x), "f"(v.y), "f"(v.z), "f"(v.w)
                 : "memory");
}

__device__ __forceinline__ float2 ldg2(const float* p) {
    float2 v;
    asm volatile("ld.global.nc.v2.f32 {%0, %1}, [%2];"
                 : "=f"(v.x), "=f"(v.y) : "l"(p));
    return v;
}

// block: (48, 2) -> 48 channel-pair lanes x 2 w positions
// grid:  (112, 4, 16)
__global__ __launch_bounds__(96, 12) void dwconv_kernel(
    const float* __restrict__ x,
    const float* __restrict__ ker,   // 18 floats [3][3][1][2]
    const float* __restrict__ bias,  // 192 floats
    float* __restrict__ out)
{
    const int c2 = threadIdx.x;                    // 0..47 channel pair
    const int w  = blockIdx.x * 2 + threadIdx.y;   // 0..223
    const int h0 = blockIdx.y * HCH;
    const int b  = blockIdx.z;

    // Weights in registers (R4 lesson: never LDC in the hot loop on sm_103a).
    float kw[3][3][2];
#pragma unroll
    for (int i = 0; i < 3; i++)
#pragma unroll
        for (int j = 0; j < 3; j++)
#pragma unroll
            for (int m = 0; m < 2; m++)
                kw[i][j][m] = __ldg(&ker[(i * 3 + j) * 2 + m]);

    // Thread covers output channels [4*c2, 4*c2+4): {c0m0, c0m1, c1m0, c1m1}
    const float4 bb = *reinterpret_cast<const float4*>(&bias[4 * c2]);

    const bool wlo = (w > 0);
    const bool whi = (w < WW - 1);

    const size_t xstride = (size_t)WW * CIN;    // floats per input row
    const size_t ostride = (size_t)WW * COUT;   // floats per output row

    const float* xrow0 = x + (((size_t)b * HH) * WW + w) * CIN + 2 * c2;  // h=0
    float* orow0 = out + (((size_t)b * HH) * WW + w) * COUT + 4 * c2;

    const float2 z2 = make_float2(0.f, 0.f);
    const int hmax = h0 + HCH;   // highest row index consumed by this chunk

    // Checked row load (prolog + tail): zeros when hh out of [0, HH).
    auto load_row = [&](float2(&r)[3], int hh) {
        if ((unsigned)hh < (unsigned)HH) {
            const float* p = xrow0 + (size_t)hh * xstride;
            r[0] = wlo ? ldg2(p - CIN) : z2;
            r[1] = ldg2(p);
            r[2] = whi ? ldg2(p + CIN) : z2;
        } else {
            r[0] = z2; r[1] = z2; r[2] = z2;
        }
    };

    // Unchecked row load for the clamp-free main loop (row known in-bounds).
    auto load_row_fast = [&](float2(&r)[3], const float* p) {
        r[0] = wlo ? ldg2(p - CIN) : z2;
        r[1] = ldg2(p);
        r[2] = whi ? ldg2(p + CIN) : z2;
    };

    auto compute = [&](const float2(&rm)[3], const float2(&rz)[3],
                       const float2(&rp)[3], float* po) {
        float a00 = bb.x, a01 = bb.y, a10 = bb.z, a11 = bb.w;
#pragma unroll
        for (int dw = 0; dw < 3; dw++) {
            const float k0 = kw[0][dw][0], k1 = kw[0][dw][1];
            a00 = fmaf(rm[dw].x, k0, a00); a01 = fmaf(rm[dw].x, k1, a01);
            a10 = fmaf(rm[dw].y, k0, a10); a11 = fmaf(rm[dw].y, k1, a11);
        }
#pragma unroll
        for (int dw = 0; dw < 3; dw++) {
            const float k0 = kw[1][dw][0], k1 = kw[1][dw][1];
            a00 = fmaf(rz[dw].x, k0, a00); a01 = fmaf(rz[dw].x, k1, a01);
            a10 = fmaf(rz[dw].y, k0, a10); a11 = fmaf(rz[dw].y, k1, a11);
        }
#pragma unroll
        for (int dw = 0; dw < 3; dw++) {
            const float k0 = kw[2][dw][0], k1 = kw[2][dw][1];
            a00 = fmaf(rp[dw].x, k0, a00); a01 = fmaf(rp[dw].x, k1, a01);
            a10 = fmaf(rp[dw].y, k0, a10); a11 = fmaf(rp[dw].y, k1, a11);
        }
        stcs4(po, make_float4(a00, a01, a10, a11));
    };

    // 5-buffer rotation; prolog loads rows h0-1 .. h0+2 (checked: h0-1 may be -1).
    float2 r0[3], r1[3], r2[3], r3[3], r4[3];
    load_row(r0, h0 - 1);
    load_row(r1, h0);
    load_row(r2, h0 + 1);
    load_row(r3, h0 + 2);

    // Main loop: 50 steps (h0 .. h0+49), prefetching rows h0+3 .. h0+52.
    // h0 <= 168 for every chunk -> h0+52 <= 220 < 224: always in-bounds.
    const float* pf = xrow0 + (size_t)(h0 + 3) * xstride;  // next prefetch row
    float* po = orow0 + (size_t)h0 * ostride;              // next store row

    auto step_fast = [&](float2(&rm)[3], float2(&rz)[3], float2(&rp)[3],
                         float2(&rn)[3]) {
        load_row_fast(rn, pf);
        pf += xstride;
        compute(rm, rz, rp, po);
        po += ostride;
    };

#pragma unroll 1
    for (int it = 0; it < 10; ++it) {   // 10 x 5 = 50 rows
        step_fast(r0, r1, r2, r4);
        step_fast(r1, r2, r3, r0);
        step_fast(r2, r3, r4, r1);
        step_fast(r3, r4, r0, r2);
        step_fast(r4, r0, r1, r3);
    }

    // Tail: 6 steps (h0+50 .. h0+55), prefetch clamped (dead rows -> zeros).
    auto step_tail = [&](float2(&rm)[3], float2(&rz)[3], float2(&rp)[3],
                         float2(&rn)[3], int h) {
        const int hpre = h + 3;
        load_row(rn, (hpre <= hmax) ? hpre : HH);  // hh=HH -> zero fill, no traffic
        compute(rm, rz, rp, orow0 + (size_t)h * ostride);
    };

    int h = h0 + 50;
    step_tail(r0, r1, r2, r4, h); ++h;
    step_tail(r1, r2, r3, r0, h); ++h;
    step_tail(r2, r3, r4, r1, h); ++h;
    step_tail(r3, r4, r0, r2, h); ++h;
    step_tail(r4, r0, r1, r3, h); ++h;
    step_tail(r0, r1, r2, r4, h);
}

extern "C" void kernel_launch(void* const* d_in, const int* in_sizes, int n_in,
                              void* d_out, int out_size) {
    const float* x    = (const float*)d_in[0];
    const float* ker  = (const float*)d_in[1];
    const float* bias = (const float*)d_in[2];
    float* out        = (float*)d_out;

    dim3 block(48, 2, 1);
    dim3 grid(WW / 2, HH / HCH, BATCH);
    dwconv_kernel<<<grid, block>>>(x, ker, bias, out);
}

// round 14
// speedup vs baseline: 1.0817x; 1.0817x over previous
#include <cuda_runtime.h>

// Depthwise 3x3 conv, SAME padding, channel multiplier 2, NHWC fp32.
// x: [16,224,224,96], kernel: [3,3,1,2], bias: [192], out: [16,224,224,192]
// out[b,h,w,c*2+m] = sum_{dh,dw} x[b,h+dh-1,w+dw-1,c] * k[dh,dw,0,m] + bias[c*2+m]
//
// R14: R11 exactly (cache-policy experiment of R12 reverted — st.cs regressed)
// with HCH 56 -> 28: 14336 CTAs, T_CTA halved, cutting end-of-grid wave-tail
// quantization (R11: 4.04 waves of 37us CTAs). Costs +3.4% input halo traffic.
// Tail steps now also use running pointers.

#define BATCH 16
#define HH 224
#define WW 224
#define CIN 96
#define COUT 192
#define HCH 28   // h rows per CTA (224/28 = 8 chunks)

// block: (48, 2) -> 48 channel-pair lanes x 2 w positions
// grid:  (112, 8, 16)
__global__ __launch_bounds__(96, 12) void dwconv_kernel(
    const float* __restrict__ x,
    const float* __restrict__ ker,   // 18 floats [3][3][1][2]
    const float* __restrict__ bias,  // 192 floats
    float* __restrict__ out)
{
    const int c2 = threadIdx.x;                    // 0..47 channel pair
    const int w  = blockIdx.x * 2 + threadIdx.y;   // 0..223
    const int h0 = blockIdx.y * HCH;
    const int b  = blockIdx.z;

    // Weights in registers (R4 lesson: never LDC in the hot loop on sm_103a).
    float kw[3][3][2];
#pragma unroll
    for (int i = 0; i < 3; i++)
#pragma unroll
        for (int j = 0; j < 3; j++)
#pragma unroll
            for (int m = 0; m < 2; m++)
                kw[i][j][m] = __ldg(&ker[(i * 3 + j) * 2 + m]);

    // Thread covers output channels [4*c2, 4*c2+4): {c0m0, c0m1, c1m0, c1m1}
    const float4 bb = *reinterpret_cast<const float4*>(&bias[4 * c2]);

    const bool wlo = (w > 0);
    const bool whi = (w < WW - 1);

    const size_t xstride = (size_t)WW * CIN;    // floats per input row
    const size_t ostride = (size_t)WW * COUT;   // floats per output row

    const float* xrow0 = x + (((size_t)b * HH) * WW + w) * CIN + 2 * c2;  // h=0
    float* orow0 = out + (((size_t)b * HH) * WW + w) * COUT + 4 * c2;

    const float2 z2 = make_float2(0.f, 0.f);
    // Highest input row this chunk consumes, clamped to the image.
    const int hlast = (h0 + HCH < HH) ? (h0 + HCH) : (HH - 1);

    // Checked row load (prolog only): zeros when hh out of [0, HH).
    auto load_row = [&](float2(&r)[3], int hh) {
        if ((unsigned)hh < (unsigned)HH) {
            const float* p = xrow0 + (size_t)hh * xstride;
            r[0] = wlo ? *reinterpret_cast<const float2*>(p - CIN) : z2;
            r[1] = *reinterpret_cast<const float2*>(p);
            r[2] = whi ? *reinterpret_cast<const float2*>(p + CIN) : z2;
        } else {
            r[0] = z2; r[1] = z2; r[2] = z2;
        }
    };

    // Unchecked row load (row known in-bounds), pointer-addressed.
    auto load_row_fast = [&](float2(&r)[3], const float* p) {
        r[0] = wlo ? *reinterpret_cast<const float2*>(p - CIN) : z2;
        r[1] = *reinterpret_cast<const float2*>(p);
        r[2] = whi ? *reinterpret_cast<const float2*>(p + CIN) : z2;
    };

    auto compute = [&](const float2(&rm)[3], const float2(&rz)[3],
                       const float2(&rp)[3], float* po) {
        float a00 = bb.x, a01 = bb.y, a10 = bb.z, a11 = bb.w;
#pragma unroll
        for (int dw = 0; dw < 3; dw++) {
            const float k0 = kw[0][dw][0], k1 = kw[0][dw][1];
            a00 = fmaf(rm[dw].x, k0, a00); a01 = fmaf(rm[dw].x, k1, a01);
            a10 = fmaf(rm[dw].y, k0, a10); a11 = fmaf(rm[dw].y, k1, a11);
        }
#pragma unroll
        for (int dw = 0; dw < 3; dw++) {
            const float k0 = kw[1][dw][0], k1 = kw[1][dw][1];
            a00 = fmaf(rz[dw].x, k0, a00); a01 = fmaf(rz[dw].x, k1, a01);
            a10 = fmaf(rz[dw].y, k0, a10); a11 = fmaf(rz[dw].y, k1, a11);
        }
#pragma unroll
        for (int dw = 0; dw < 3; dw++) {
            const float k0 = kw[2][dw][0], k1 = kw[2][dw][1];
            a00 = fmaf(rp[dw].x, k0, a00); a01 = fmaf(rp[dw].x, k1, a01);
            a10 = fmaf(rp[dw].y, k0, a10); a11 = fmaf(rp[dw].y, k1, a11);
        }
        *reinterpret_cast<float4*>(po) = make_float4(a00, a01, a10, a11);
    };

    // 5-buffer rotation; prolog loads rows h0-1 .. h0+2 (h0-1 may be -1).
    float2 r0[3], r1[3], r2[3], r3[3], r4[3];
    load_row(r0, h0 - 1);
    load_row(r1, h0);
    load_row(r2, h0 + 1);
    load_row(r3, h0 + 2);

    // Running pointers for prefetch (row h0+3 first) and store (row h0 first).
    const float* pf = xrow0 + (size_t)(h0 + 3) * xstride;
    float* po = orow0 + (size_t)h0 * ostride;
    int hpre = h0 + 3;   // row the next prefetch targets

    // Main loop: 22 clamp-free steps (computes h0..h0+21, prefetches
    // h0+3..h0+24; h0 <= 196 -> h0+24 <= 220 < 224: always in-bounds).
    auto step_fast = [&](float2(&rm)[3], float2(&rz)[3], float2(&rp)[3],
                         float2(&rn)[3]) {
        load_row_fast(rn, pf);
        pf += xstride; ++hpre;
        compute(rm, rz, rp, po);
        po += ostride;
    };

#pragma unroll 1
    for (int it = 0; it < 4; ++it) {   // 4 x 5 = 20 rows (rotation period 5)
        step_fast(r0, r1, r2, r4);
        step_fast(r1, r2, r3, r0);
        step_fast(r2, r3, r4, r1);
        step_fast(r3, r4, r0, r2);
        step_fast(r4, r0, r1, r3);
    }
    step_fast(r0, r1, r2, r4);         // k=20
    step_fast(r1, r2, r3, r0);         // k=21

    // Tail: 6 steps (computes h0+22..h0+27), prefetch clamped past hlast.
    auto step_tail = [&](float2(&rm)[3], float2(&rz)[3], float2(&rp)[3],
                         float2(&rn)[3]) {
        if (hpre <= hlast) {
            load_row_fast(rn, pf);
        } else {
            rn[0] = z2; rn[1] = z2; rn[2] = z2;
        }
        pf += xstride; ++hpre;
        compute(rm, rz, rp, po);
        po += ostride;
    };

    step_tail(r2, r3, r4, r1);   // k=22
    step_tail(r3, r4, r0, r2);   // k=23
    step_tail(r4, r0, r1, r3);   // k=24
    step_tail(r0, r1, r2, r4);   // k=25
    step_tail(r1, r2, r3, r0);   // k=26
    step_tail(r2, r3, r4, r1);   // k=27
}

extern "C" void kernel_launch(void* const* d_in, const int* in_sizes, int n_in,
                              void* d_out, int out_size) {
    const float* x    = (const float*)d_in[0];
    const float* ker  = (const float*)d_in[1];
    const float* bias = (const float*)d_in[2];
    float* out        = (float*)d_out;

    dim3 block(48, 2, 1);
    dim3 grid(WW / 2, HH / HCH, BATCH);
    dwconv_kernel<<<grid, block>>>(x, ker, bias, out);
}